// round 7
// baseline (speedup 1.0000x reference)
#include <cuda_runtime.h>
#include <math.h>

// ------------------------------------------------------------------
// Problem constants
// ------------------------------------------------------------------
#define B_    4
#define C_    256
#define H_    128
#define W_    128
#define HW    (H_*W_)          // 16384
#define NTOK  (B_*HW)          // 65536
#define CB    128
#define HEADS 2
#define CD    64
#define SCALE 0.08838834764831845f
#define EPS   1e-4f

typedef unsigned long long ull;
typedef unsigned int uint32;

// round-to-nearest tf32 (kept in fp32 container)
__device__ __forceinline__ float tf32r(float v) {
    uint32 r; asm("cvt.rna.tf32.f32 %0, %1;" : "=r"(r) : "f"(v));
    return __uint_as_float(r);
}
__device__ __forceinline__ uint32 tf32u(float v) {
    uint32 r; asm("cvt.rna.tf32.f32 %0, %1;" : "=r"(r) : "f"(v));
    return r;
}
// m16n8k8 tf32 mma.sync (target-portable)
__device__ __forceinline__ void mma8(float* d, const uint32* a, const uint32* b) {
    asm volatile("mma.sync.aligned.m16n8k8.row.col.f32.tf32.tf32.f32 "
        "{%0,%1,%2,%3}, {%4,%5,%6,%7}, {%8,%9}, {%0,%1,%2,%3};"
        : "+f"(d[0]), "+f"(d[1]), "+f"(d[2]), "+f"(d[3])
        : "r"(a[0]), "r"(a[1]), "r"(a[2]), "r"(a[3]), "r"(b[0]), "r"(b[1]));
}

// ------------------------------------------------------------------
// Scratch
// ------------------------------------------------------------------
__device__ float g_xnh[(size_t)NTOK * C_];        // LN output hi (tf32)
__device__ float g_xnl[(size_t)NTOK * C_];        // LN output lo (tf32)
__device__ float g_qkv[(size_t)NTOK * 3 * C_];    // [t][ qkv(3) br(2) head(2) d(64) ]
__device__ float g_xc [(size_t)NTOK * C_];        // attn+lepe, [t][c]
__device__ float g_xch[(size_t)NTOK * C_];
__device__ float g_xcl[(size_t)NTOK * C_];
__device__ float g_wqh[768 * 256];                // qkv weight^T hi [n][k]
__device__ float g_wql[768 * 256];
__device__ float g_pwh[256 * 256];                // proj weight hi [o][k]
__device__ float g_pwl[256 * 256];

__device__ __forceinline__ int win_token(int br, int win, int s) {
    int b  = win >> 5;
    int wi = win & 31;
    int y, x;
    if (br == 0) { y = s >> 2;               x = (wi << 2) + (s & 3); }
    else         { y = (wi << 2) + (s >> 7); x = s & 127; }
    return b * HW + y * W_ + x;
}

// ------------------------------------------------------------------
// 1) LayerNorm -> hi/lo tf32 splits
// ------------------------------------------------------------------
__global__ void __launch_bounds__(256) ln_kernel(const float* __restrict__ x,
                                                 const float* __restrict__ gam,
                                                 const float* __restrict__ bet) {
    __shared__ float xs[C_][33];
    __shared__ float mu_s[32], rs_s[32];
    int tid = threadIdx.x;
    int tx = tid & 31, ty = tid >> 5;
    int t0 = blockIdx.x * 32;
    int b  = t0 / HW;
    int pp = t0 - b * HW;
    const float* xb = x + (size_t)b * C_ * HW + pp + tx;
    #pragma unroll
    for (int c = ty; c < C_; c += 8)
        xs[c][tx] = xb[(size_t)c * HW];
    __syncthreads();
    if (tid < 32) {
        float s = 0.f, s2 = 0.f;
        #pragma unroll 8
        for (int c = 0; c < C_; c++) { float v = xs[c][tid]; s += v; s2 += v * v; }
        float mu  = s * (1.0f / C_);
        float var = s2 * (1.0f / C_) - mu * mu;
        mu_s[tid] = mu;
        rs_s[tid] = rsqrtf(var + EPS);
    }
    __syncthreads();
    for (int idx = tid; idx < 32 * C_; idx += 256) {
        int c = idx & 255, tk = idx >> 8;
        float v = (xs[c][tk] - mu_s[tk]) * rs_s[tk] * gam[c] + bet[c];
        float h = tf32r(v);
        size_t o = (size_t)(t0 + tk) * C_ + c;
        g_xnh[o] = h;
        g_xnl[o] = tf32r(v - h);
    }
}

// ------------------------------------------------------------------
// 1b) weight splits
// ------------------------------------------------------------------
__global__ void __launch_bounds__(256) w_split(const float* __restrict__ wqkv,
                                               const float* __restrict__ projw) {
    int idx = blockIdx.x * 256 + threadIdx.x;
    if (idx < 768 * 256) {
        int n = idx >> 8, k = idx & 255;
        float v = wqkv[(size_t)k * 768 + n];
        float h = tf32r(v);
        g_wqh[idx] = h;
        g_wql[idx] = tf32r(v - h);
    }
    if (idx < 256 * 256) {
        float v = projw[idx];
        float h = tf32r(v);
        g_pwh[idx] = h;
        g_pwl[idx] = tf32r(v - h);
    }
}

// ------------------------------------------------------------------
// 1c) xc hi/lo split
// ------------------------------------------------------------------
__global__ void __launch_bounds__(256) xc_split() {
    size_t idx = (size_t)blockIdx.x * 256 + threadIdx.x;
    float4 v = ((const float4*)g_xc)[idx];
    float4 h, l;
    h.x = tf32r(v.x); l.x = tf32r(v.x - h.x);
    h.y = tf32r(v.y); l.y = tf32r(v.y - h.y);
    h.z = tf32r(v.z); l.z = tf32r(v.z - h.z);
    h.w = tf32r(v.w); l.w = tf32r(v.w - h.w);
    ((float4*)g_xch)[idx] = h;
    ((float4*)g_xcl)[idx] = l;
}

// ------------------------------------------------------------------
// mma.sync 3xTF32 GEMM core (128x128 tile, K=256)
// ------------------------------------------------------------------
#define ASH 0
#define ASL 4608
#define BSH 9216
#define BSL 13824
#define SMEM_GEMM_BYTES (18432 * 4)

extern __shared__ float sm_g[];

__device__ __forceinline__ void mma_mainloop(
        const float* __restrict__ Ah, const float* __restrict__ Al,
        const float* __restrict__ Bh, const float* __restrict__ Bl,
        int m0, int n0, float acc[4][4][4]) {
    int tid  = threadIdx.x;
    int wid  = tid >> 5, lane = tid & 31;
    int wm   = (wid & 1) * 64;
    int wn   = (wid >> 1) * 32;
    int grp  = lane >> 2, tig = lane & 3;

    for (int ck = 0; ck < 8; ck++) {
        int k0 = ck * 32;
        __syncthreads();
        #pragma unroll
        for (int idx = tid; idx < 1024; idx += 256) {
            int r = idx >> 3, q = (idx & 7) * 4;
            size_t ga = (size_t)(m0 + r) * 256 + k0 + q;
            size_t gb = (size_t)(n0 + r) * 256 + k0 + q;
            int so = r * 36 + q;
            *(float4*)&sm_g[ASH + so] = *(const float4*)(Ah + ga);
            *(float4*)&sm_g[ASL + so] = *(const float4*)(Al + ga);
            *(float4*)&sm_g[BSH + so] = *(const float4*)(Bh + gb);
            *(float4*)&sm_g[BSL + so] = *(const float4*)(Bl + gb);
        }
        __syncthreads();
        #pragma unroll
        for (int ks = 0; ks < 4; ks++) {
            int kk = ks * 8;
            uint32 bh[4][2], bl[4][2];
            #pragma unroll
            for (int j = 0; j < 4; j++) {
                int nb = (wn + j * 8 + grp) * 36 + kk + tig;
                bh[j][0] = __float_as_uint(sm_g[BSH + nb]);
                bh[j][1] = __float_as_uint(sm_g[BSH + nb + 4]);
                bl[j][0] = __float_as_uint(sm_g[BSL + nb]);
                bl[j][1] = __float_as_uint(sm_g[BSL + nb + 4]);
            }
            #pragma unroll
            for (int i = 0; i < 4; i++) {
                int mb = (wm + i * 16 + grp) * 36 + kk + tig;
                uint32 ah[4], al[4];
                ah[0] = __float_as_uint(sm_g[ASH + mb]);
                ah[1] = __float_as_uint(sm_g[ASH + mb + 8 * 36]);
                ah[2] = __float_as_uint(sm_g[ASH + mb + 4]);
                ah[3] = __float_as_uint(sm_g[ASH + mb + 8 * 36 + 4]);
                al[0] = __float_as_uint(sm_g[ASL + mb]);
                al[1] = __float_as_uint(sm_g[ASL + mb + 8 * 36]);
                al[2] = __float_as_uint(sm_g[ASL + mb + 4]);
                al[3] = __float_as_uint(sm_g[ASL + mb + 8 * 36 + 4]);
                #pragma unroll
                for (int j = 0; j < 4; j++) {
                    mma8(acc[i][j], ah, bh[j]);
                    mma8(acc[i][j], ah, bl[j]);
                    mma8(acc[i][j], al, bh[j]);
                }
            }
        }
    }
    __syncthreads();
    #pragma unroll
    for (int i = 0; i < 4; i++)
        #pragma unroll
        for (int j = 0; j < 4; j++) {
            int m = wm + i * 16 + grp;
            int n = wn + j * 8 + tig * 2;
            sm_g[m * 129 + n]             = acc[i][j][0];
            sm_g[m * 129 + n + 1]         = acc[i][j][1];
            sm_g[(m + 8) * 129 + n]       = acc[i][j][2];
            sm_g[(m + 8) * 129 + n + 1]   = acc[i][j][3];
        }
    __syncthreads();
}

__global__ void __launch_bounds__(256) gemm_qkv_mma() {
    float acc[4][4][4] = {};
    int m0 = blockIdx.y * 128;
    int n0 = blockIdx.x * 128;
    mma_mainloop(g_xnh, g_xnl, g_wqh, g_wql, m0, n0, acc);
    int tid = threadIdx.x;
    for (int i = tid; i < 128 * 128; i += 256) {
        int m = i >> 7, n = i & 127;
        int ng = n0 + n;
        int part = ng >> 8, rm = ng & 255;
        int pn = (part << 8) + ((rm >> 7) << 7) + ((rm & 1) << 6) + ((rm & 127) >> 1);
        g_qkv[(size_t)(m0 + m) * 768 + pn] = sm_g[m * 129 + n];
    }
}

__global__ void __launch_bounds__(256) gemm_proj_mma(const float* __restrict__ Pb,
                                                     float* __restrict__ out) {
    float acc[4][4][4] = {};
    int m0 = blockIdx.y * 128;
    int n0 = blockIdx.x * 128;
    mma_mainloop(g_xch, g_xcl, g_pwh, g_pwl, m0, n0, acc);
    int tid = threadIdx.x;
    int b  = m0 >> 14;
    int pp = m0 & (HW - 1);
    int mm = tid & 127;
    int oh = tid >> 7;
    float* Op = out + (size_t)b * C_ * HW + pp + mm;
    #pragma unroll 4
    for (int oo = 0; oo < 64; oo++) {
        int o = n0 + oh * 64 + oo;
        Op[(size_t)o * HW] = sm_g[mm * 129 + oh * 64 + oo] + Pb[o];
    }
}

// ------------------------------------------------------------------
// 3) LePE depthwise 3x3 — branch templated (all index math constant)
// ------------------------------------------------------------------
template<int BR>
__global__ void lepe_t(const float* __restrict__ wt, const float* __restrict__ bs) {
    constexpr int HSP = (BR == 0) ? 128 : 4;
    constexpr int WSP = (BR == 0) ? 4   : 128;
    int cc  = threadIdx.x;                                  // 0..127
    int s   = blockIdx.x * blockDim.y + threadIdx.y;        // 0..511
    int win = blockIdx.y;                                   // 0..127
    int b   = win >> 5;
    int wi  = win & 31;
    const float* w = wt + cc * 9;
    float bias = bs[cc];
    int i = s / WSP, j = s % WSP;                           // constexpr shifts
    int vcol = 512 + BR * 128 + ((cc & 1) << 6) + (cc >> 1);
    float acc = bias;
    #pragma unroll
    for (int ki = 0; ki < 3; ki++) {
        int ii = i + ki - 1;
        if (ii < 0 || ii >= HSP) continue;
        #pragma unroll
        for (int kj = 0; kj < 3; kj++) {
            int jj = j + kj - 1;
            if (jj < 0 || jj >= WSP) continue;
            int ss = ii * WSP + jj;
            int y, x;
            if (BR == 0) { y = ss >> 2;               x = (wi << 2) + (ss & 3); }
            else         { y = (wi << 2) + (ss >> 7); x = ss & 127; }
            int tn = b * HW + y * W_ + x;
            acc += w[ki * 3 + kj] * g_qkv[(size_t)tn * 768 + vcol];
        }
    }
    int y, x;
    if (BR == 0) { y = s >> 2;              x = (wi << 2) + (s & 3); }
    else         { y = (wi << 2) + (s >> 7); x = s & 127; }
    int t = b * HW + y * W_ + x;
    g_xc[(size_t)t * C_ + BR * 128 + cc] = acc;
}

// ------------------------------------------------------------------
// 4) Attention via mma.sync tf32.
//    Block = (qtile 64, head, branch*win), 256 threads (8 warps).
//    QK^T: 3xTF32. softmax fp32 (unnormalized exp + row inv-sums).
//    PV: P->tf32 once, V hi/lo (2 mma). Strides: S=516, Q/K/V=68
//    so all fragment accesses hit banks (4*grp+tig)%32 -> conflict-free.
// ------------------------------------------------------------------
#define SST   516
#define TST   68
#define OFF_S    0
#define OFF_QH   33024
#define OFF_QL   (OFF_QH + 64 * TST)
#define OFF_KH   (OFF_QL + 64 * TST)     // reused as V hi
#define OFF_KL   (OFF_KH + 64 * TST)     // reused as V lo
#define OFF_RI   (OFF_KL + 64 * TST)
#define SMEM_ATTN_FLOATS (OFF_RI + 64)

extern __shared__ float sm_a[];
__global__ void __launch_bounds__(256) attn_mma() {
    int qt   = blockIdx.x;              // 0..7
    int head = blockIdx.y;              // 0..1
    int wb   = blockIdx.z;              // 0..255
    int br   = wb >> 7;
    int win  = wb & 127;
    int tid  = threadIdx.x;
    int wid  = tid >> 5, lane = tid & 31;
    int grp  = lane >> 2, tig = lane & 3;
    int wm   = (wid & 3) * 16;
    int wn   = (wid >> 2) * 32;
    int base = br * 128 + head * 64;

    // ---- load Q tile (scaled, hi/lo) ----
    for (int idx = tid; idx < 64 * 64; idx += 256) {
        int r = idx >> 6, d = idx & 63;
        int t = win_token(br, win, qt * 64 + r);
        float v = g_qkv[(size_t)t * 768 + base + d] * SCALE;
        float h = tf32r(v);
        sm_a[OFF_QH + r * TST + d] = h;
        sm_a[OFF_QL + r * TST + d] = tf32r(v - h);
    }

    // ---- S = Q K^T over 8 key chunks of 64 ----
    for (int ck = 0; ck < 8; ck++) {
        __syncthreads();
        for (int idx = tid; idx < 64 * 64; idx += 256) {
            int key = idx >> 6, d = idx & 63;
            int t = win_token(br, win, ck * 64 + key);
            float v = g_qkv[(size_t)t * 768 + 256 + base + d];
            float h = tf32r(v);
            sm_a[OFF_KH + key * TST + d] = h;
            sm_a[OFF_KL + key * TST + d] = tf32r(v - h);
        }
        __syncthreads();
        float acc[4][4] = {};
        #pragma unroll
        for (int ks = 0; ks < 8; ks++) {
            int kk = ks * 8;
            uint32 ah[4], al[4];
            int mb = (wm + grp) * TST + kk + tig;
            ah[0] = __float_as_uint(sm_a[OFF_QH + mb]);
            ah[1] = __float_as_uint(sm_a[OFF_QH + mb + 8 * TST]);
            ah[2] = __float_as_uint(sm_a[OFF_QH + mb + 4]);
            ah[3] = __float_as_uint(sm_a[OFF_QH + mb + 8 * TST + 4]);
            al[0] = __float_as_uint(sm_a[OFF_QL + mb]);
            al[1] = __float_as_uint(sm_a[OFF_QL + mb + 8 * TST]);
            al[2] = __float_as_uint(sm_a[OFF_QL + mb + 4]);
            al[3] = __float_as_uint(sm_a[OFF_QL + mb + 8 * TST + 4]);
            #pragma unroll
            for (int j = 0; j < 4; j++) {
                int nb = (wn + j * 8 + grp) * TST + kk + tig;
                uint32 bh[2], bl[2];
                bh[0] = __float_as_uint(sm_a[OFF_KH + nb]);
                bh[1] = __float_as_uint(sm_a[OFF_KH + nb + 4]);
                bl[0] = __float_as_uint(sm_a[OFF_KL + nb]);
                bl[1] = __float_as_uint(sm_a[OFF_KL + nb + 4]);
                mma8(acc[j], ah, bh);
                mma8(acc[j], ah, bl);
                mma8(acc[j], al, bh);
            }
        }
        #pragma unroll
        for (int j = 0; j < 4; j++) {
            int col = ck * 64 + wn + j * 8 + 2 * tig;
            sm_a[OFF_S + (wm + grp) * SST + col]         = acc[j][0];
            sm_a[OFF_S + (wm + grp) * SST + col + 1]     = acc[j][1];
            sm_a[OFF_S + (wm + 8 + grp) * SST + col]     = acc[j][2];
            sm_a[OFF_S + (wm + 8 + grp) * SST + col + 1] = acc[j][3];
        }
    }
    __syncthreads();

    // ---- softmax: row max, exp (kept unnormalized), inv row sum ----
    for (int r = wid * 8; r < wid * 8 + 8; r++) {
        float* row = sm_a + OFF_S + r * SST;
        float m = -1e30f;
        for (int c = lane; c < 512; c += 32) m = fmaxf(m, row[c]);
        #pragma unroll
        for (int o = 16; o; o >>= 1) m = fmaxf(m, __shfl_xor_sync(0xffffffffu, m, o));
        float ssum = 0.f;
        for (int c = lane; c < 512; c += 32) {
            float e = __expf(row[c] - m);
            row[c] = e;
            ssum += e;
        }
        #pragma unroll
        for (int o = 16; o; o >>= 1) ssum += __shfl_xor_sync(0xffffffffu, ssum, o);
        if (lane == 0) sm_a[OFF_RI + r] = 1.0f / ssum;
    }

    // ---- O = P V over 8 V chunks of 64 keys (V transposed, hi/lo) ----
    float oacc[4][4] = {};
    for (int ck = 0; ck < 8; ck++) {
        __syncthreads();
        for (int idx = tid; idx < 256; idx += 256) { }   // (no-op, keep structure)
        for (int idx = tid; idx < 64 * 4; idx += 256) {
            int key = idx >> 2, dg = (idx & 3) * 16;
            int t = win_token(br, win, ck * 64 + key);
            const float* vp = g_qkv + (size_t)t * 768 + 512 + base + dg;
            #pragma unroll
            for (int s = 0; s < 16; s++) {
                float v = vp[s];
                float h = tf32r(v);
                sm_a[OFF_KH + (dg + s) * TST + key] = h;
                sm_a[OFF_KL + (dg + s) * TST + key] = tf32r(v - h);
            }
        }
        __syncthreads();
        #pragma unroll
        for (int ks = 0; ks < 8; ks++) {
            int kk = ks * 8;
            uint32 a[4];
            int sb = OFF_S + (wm + grp) * SST + ck * 64 + kk + tig;
            a[0] = tf32u(sm_a[sb]);
            a[1] = tf32u(sm_a[sb + 8 * SST]);
            a[2] = tf32u(sm_a[sb + 4]);
            a[3] = tf32u(sm_a[sb + 8 * SST + 4]);
            #pragma unroll
            for (int j = 0; j < 4; j++) {
                int nb = (wn + j * 8 + grp) * TST + kk + tig;
                uint32 bh[2], bl[2];
                bh[0] = __float_as_uint(sm_a[OFF_KH + nb]);
                bh[1] = __float_as_uint(sm_a[OFF_KH + nb + 4]);
                bl[0] = __float_as_uint(sm_a[OFF_KL + nb]);
                bl[1] = __float_as_uint(sm_a[OFF_KL + nb + 4]);
                mma8(oacc[j], a, bh);
                mma8(oacc[j], a, bl);
            }
        }
    }

    // ---- epilogue: normalize rows, accumulate onto LePE in g_xc ----
    __syncthreads();
    float i0 = sm_a[OFF_RI + wm + grp];
    float i1 = sm_a[OFF_RI + wm + 8 + grp];
    int t0 = win_token(br, win, qt * 64 + wm + grp);
    int t1 = win_token(br, win, qt * 64 + wm + 8 + grp);
    size_t g0 = (size_t)t0 * C_ + br * 128 + head;
    size_t g1 = (size_t)t1 * C_ + br * 128 + head;
    #pragma unroll
    for (int j = 0; j < 4; j++) {
        int d = wn + j * 8 + 2 * tig;
        g_xc[g0 + 2 * d]       += oacc[j][0] * i0;
        g_xc[g0 + 2 * (d + 1)] += oacc[j][1] * i0;
        g_xc[g1 + 2 * d]       += oacc[j][2] * i1;
        g_xc[g1 + 2 * (d + 1)] += oacc[j][3] * i1;
    }
}

// ------------------------------------------------------------------
// launch
// ------------------------------------------------------------------
extern "C" void kernel_launch(void* const* d_in, const int* in_sizes, int n_in,
                              void* d_out, int out_size) {
    const float* x       = (const float*)d_in[0];
    const float* ln_g    = (const float*)d_in[1];
    const float* ln_b    = (const float*)d_in[2];
    const float* w_qkv   = (const float*)d_in[3];
    const float* lepe_w1 = (const float*)d_in[4];
    const float* lepe_b1 = (const float*)d_in[5];
    const float* lepe_w2 = (const float*)d_in[6];
    const float* lepe_b2 = (const float*)d_in[7];
    const float* proj_w  = (const float*)d_in[8];
    const float* proj_b  = (const float*)d_in[9];
    float* out = (float*)d_out;

    size_t smem_attn = (size_t)SMEM_ATTN_FLOATS * sizeof(float);   // ~202 KB
    cudaFuncSetAttribute(attn_mma, cudaFuncAttributeMaxDynamicSharedMemorySize,
                         (int)smem_attn);
    cudaFuncSetAttribute(gemm_qkv_mma,  cudaFuncAttributeMaxDynamicSharedMemorySize, SMEM_GEMM_BYTES);
    cudaFuncSetAttribute(gemm_proj_mma, cudaFuncAttributeMaxDynamicSharedMemorySize, SMEM_GEMM_BYTES);

    ln_kernel  <<< NTOK / 32, 256 >>>(x, ln_g, ln_b);
    w_split    <<< 768, 256 >>>(w_qkv, proj_w);
    gemm_qkv_mma <<< dim3(6, 512), 256, SMEM_GEMM_BYTES >>>();
    lepe_t<0>  <<< dim3(128, 128), dim3(128, 4) >>>(lepe_w1, lepe_b1);
    lepe_t<1>  <<< dim3(128, 128), dim3(128, 4) >>>(lepe_w2, lepe_b2);
    attn_mma   <<< dim3(8, 2, 256), 256, smem_attn >>>();
    xc_split   <<< (NTOK * C_ / 4) / 256, 256 >>>();
    gemm_proj_mma <<< dim3(2, 512), 256, SMEM_GEMM_BYTES >>>(proj_b, out);
}

// round 8
// speedup vs baseline: 2.6709x; 2.6709x over previous
#include <cuda_runtime.h>
#include <math.h>

#define B_    4
#define C_    256
#define H_    128
#define W_    128
#define HW    (H_*W_)          // 16384
#define NTOK  (B_*HW)          // 65536
#define SCALE 0.08838834764831845f
#define EPS   1e-4f

typedef unsigned long long ull;
typedef unsigned int uint32;
typedef unsigned short ushort;

// ---------------- bf16 helpers ----------------
__device__ __forceinline__ uint32 pkbf(float lo, float hi) {
    uint32 d; asm("cvt.rn.bf16x2.f32 %0, %1, %2;" : "=r"(d) : "f"(hi), "f"(lo)); return d;
}
__device__ __forceinline__ float bflo(uint32 w){ return __uint_as_float(w << 16); }
__device__ __forceinline__ float bfhi(uint32 w){ return __uint_as_float(w & 0xffff0000u); }

// bf16 m16n8k16 mma (portable PTX, no sm_103a features)
__device__ __forceinline__ void mmabf(float* d, const uint32* a, uint32 b0, uint32 b1) {
    asm volatile("mma.sync.aligned.m16n8k16.row.col.f32.bf16.bf16.f32 "
        "{%0,%1,%2,%3}, {%4,%5,%6,%7}, {%8,%9}, {%0,%1,%2,%3};"
        : "+f"(d[0]), "+f"(d[1]), "+f"(d[2]), "+f"(d[3])
        : "r"(a[0]), "r"(a[1]), "r"(a[2]), "r"(a[3]), "r"(b0), "r"(b1));
}
__device__ __forceinline__ void ldmT(uint32& r0, uint32& r1, uint32& r2, uint32& r3, uint32 addr) {
    asm volatile("ldmatrix.sync.aligned.m8n8.x4.trans.shared.b16 {%0,%1,%2,%3}, [%4];"
        : "=r"(r0), "=r"(r1), "=r"(r2), "=r"(r3) : "r"(addr));
}
__device__ __forceinline__ uint32 smem_u32(const void* p) {
    uint32 a;
    asm("{ .reg .u64 t; cvta.to.shared.u64 t, %1; cvt.u32.u64 %0, t; }" : "=r"(a) : "l"(p));
    return a;
}

// ---------------- scratch (all bf16 planes stored as packed uint32 words) ----------------
__device__ uint32 g_xnh[(size_t)NTOK * 128];    // LN hi  [t][128w]
__device__ uint32 g_xnl[(size_t)NTOK * 128];    // LN lo
__device__ uint32 g_qkvh[(size_t)NTOK * 384];   // qkv hi [t][384w], head-deinterleaved cols
__device__ uint32 g_qkvl[(size_t)NTOK * 384];
__device__ float  g_xc [(size_t)NTOK * C_];     // attn + lepe (fp32, orig channel order)
__device__ uint32 g_xch[(size_t)NTOK * 128];
__device__ uint32 g_xcl[(size_t)NTOK * 128];
__device__ uint32 g_wqh[768 * 128];             // qkv W^T  [n][128w]
__device__ uint32 g_wql[768 * 128];
__device__ uint32 g_pwh[256 * 128];             // proj W   [o][128w]
__device__ uint32 g_pwl[256 * 128];

template<int BR>
__device__ __forceinline__ int win_tok(int win, int s) {
    int b  = win >> 5;
    int wi = win & 31;
    int y, x;
    if (BR == 0) { y = s >> 2;               x = (wi << 2) + (s & 3); }
    else         { y = (wi << 2) + (s >> 7); x = s & 127; }
    return b * HW + y * W_ + x;
}
__device__ __forceinline__ int win_tok_rt(int br, int win, int s) {
    return br == 0 ? win_tok<0>(win, s) : win_tok<1>(win, s);
}

// ---------------- 1) LayerNorm -> bf16 hi/lo planes ----------------
__global__ void __launch_bounds__(256) ln_kernel(const float* __restrict__ x,
                                                 const float* __restrict__ gam,
                                                 const float* __restrict__ bet) {
    __shared__ float xs[C_][33];
    __shared__ float mu_s[32], rs_s[32];
    int tid = threadIdx.x;
    int tx = tid & 31, ty = tid >> 5;
    int t0 = blockIdx.x * 32;
    int b  = t0 / HW;
    int pp = t0 - b * HW;
    const float* xb = x + (size_t)b * C_ * HW + pp + tx;
    #pragma unroll
    for (int c = ty; c < C_; c += 8)
        xs[c][tx] = xb[(size_t)c * HW];
    __syncthreads();
    if (tid < 32) {
        float s = 0.f, s2 = 0.f;
        #pragma unroll 8
        for (int c = 0; c < C_; c++) { float v = xs[c][tid]; s += v; s2 += v * v; }
        float mu  = s * (1.0f / C_);
        float var = s2 * (1.0f / C_) - mu * mu;
        mu_s[tid] = mu;
        rs_s[tid] = rsqrtf(var + EPS);
    }
    __syncthreads();
    for (int idx = tid; idx < 32 * 128; idx += 256) {
        int c2 = idx & 127, tk = idx >> 7;
        int c = c2 * 2;
        float v0 = (xs[c][tk]     - mu_s[tk]) * rs_s[tk] * gam[c]     + bet[c];
        float v1 = (xs[c + 1][tk] - mu_s[tk]) * rs_s[tk] * gam[c + 1] + bet[c + 1];
        uint32 hw = pkbf(v0, v1);
        uint32 lw = pkbf(v0 - bflo(hw), v1 - bfhi(hw));
        size_t o = (size_t)(t0 + tk) * 128 + c2;
        g_xnh[o] = hw;
        g_xnl[o] = lw;
    }
}

// ---------------- 1b) weight splits ----------------
__global__ void __launch_bounds__(256) w_split(const float* __restrict__ wqkv,
                                               const float* __restrict__ projw) {
    int idx = blockIdx.x * 256 + threadIdx.x;
    if (idx < 768 * 128) {
        int n = idx >> 7, kw = idx & 127;
        float v0 = wqkv[(size_t)(2 * kw) * 768 + n];
        float v1 = wqkv[(size_t)(2 * kw + 1) * 768 + n];
        uint32 hw = pkbf(v0, v1);
        g_wqh[idx] = hw;
        g_wql[idx] = pkbf(v0 - bflo(hw), v1 - bfhi(hw));
    }
    if (idx < 256 * 128) {
        float v0 = projw[idx * 2];
        float v1 = projw[idx * 2 + 1];
        uint32 hw = pkbf(v0, v1);
        g_pwh[idx] = hw;
        g_pwl[idx] = pkbf(v0 - bflo(hw), v1 - bfhi(hw));
    }
}

// ---------------- 1c) xc split ----------------
__global__ void __launch_bounds__(256) xc_split() {
    size_t idx = (size_t)blockIdx.x * 256 + threadIdx.x;   // word index
    float2 v = ((const float2*)g_xc)[idx];
    uint32 hw = pkbf(v.x, v.y);
    g_xch[idx] = hw;
    g_xcl[idx] = pkbf(v.x - bflo(hw), v.y - bfhi(hw));
}

// ---------------- bf16 3-product GEMM core (128x128 tile, K=256, chunks of 32) ----------------
// smem words: AH 0, AL 2560, BH 5120, BL 7680 (rows stride 20 words = 40 bf16)
#define GAH 0
#define GAL 2560
#define GBH 5120
#define GBL 7680
#define SMEM_GEMM_BYTES (16512 * 4)    // D staging 128x129 f32 dominates

extern __shared__ uint32 smw[];

__device__ __forceinline__ void bf_mainloop(
        const uint32* __restrict__ Ah, const uint32* __restrict__ Al,
        const uint32* __restrict__ Bh, const uint32* __restrict__ Bl,
        int m0, int n0, float acc[4][4][4]) {
    int tid  = threadIdx.x;
    int wid  = tid >> 5, lane = tid & 31;
    int wm   = (wid & 1) * 64;
    int wn   = (wid >> 1) * 32;
    int grp  = lane >> 2, tig = lane & 3;

    for (int ck = 0; ck < 8; ck++) {
        int k0w = ck * 16;
        __syncthreads();
        #pragma unroll
        for (int idx = tid; idx < 2048; idx += 256) {
            int r = idx >> 4, w = idx & 15;
            int so = r * 20 + w;
            size_t ga = (size_t)(m0 + r) * 128 + k0w + w;
            size_t gb = (size_t)(n0 + r) * 128 + k0w + w;
            smw[GAH + so] = Ah[ga];
            smw[GAL + so] = Al[ga];
            smw[GBH + so] = Bh[gb];
            smw[GBL + so] = Bl[gb];
        }
        __syncthreads();
        #pragma unroll
        for (int ks = 0; ks < 2; ks++) {
            uint32 bh[4][2], bl[4][2];
            #pragma unroll
            for (int j = 0; j < 4; j++) {
                int nb = (wn + j * 8 + grp) * 20 + ks * 8 + tig;
                bh[j][0] = smw[GBH + nb]; bh[j][1] = smw[GBH + nb + 4];
                bl[j][0] = smw[GBL + nb]; bl[j][1] = smw[GBL + nb + 4];
            }
            #pragma unroll
            for (int i = 0; i < 4; i++) {
                int mb = (wm + i * 16 + grp) * 20 + ks * 8 + tig;
                uint32 ah[4], al[4];
                ah[0] = smw[GAH + mb];        ah[1] = smw[GAH + mb + 160];
                ah[2] = smw[GAH + mb + 4];    ah[3] = smw[GAH + mb + 164];
                al[0] = smw[GAL + mb];        al[1] = smw[GAL + mb + 160];
                al[2] = smw[GAL + mb + 4];    al[3] = smw[GAL + mb + 164];
                #pragma unroll
                for (int j = 0; j < 4; j++) {
                    mmabf(acc[i][j], ah, bh[j][0], bh[j][1]);
                    mmabf(acc[i][j], ah, bl[j][0], bl[j][1]);
                    mmabf(acc[i][j], al, bh[j][0], bh[j][1]);
                }
            }
        }
    }
    // stage D
    __syncthreads();
    float* smf = (float*)smw;
    #pragma unroll
    for (int i = 0; i < 4; i++)
        #pragma unroll
        for (int j = 0; j < 4; j++) {
            int m = wm + i * 16 + grp;
            int n = wn + j * 8 + tig * 2;
            smf[m * 129 + n]           = acc[i][j][0];
            smf[m * 129 + n + 1]       = acc[i][j][1];
            smf[(m + 8) * 129 + n]     = acc[i][j][2];
            smf[(m + 8) * 129 + n + 1] = acc[i][j][3];
        }
    __syncthreads();
}

// ---------------- 2) QKV GEMM -> permuted bf16 hi/lo planes ----------------
__global__ void __launch_bounds__(256) gemm_qkv_bf() {
    float acc[4][4][4] = {};
    int m0 = blockIdx.y * 128;
    int n0 = blockIdx.x * 128;
    bf_mainloop(g_xnh, g_xnl, g_wqh, g_wql, m0, n0, acc);
    const float* smf = (const float*)smw;
    int tid = threadIdx.x;
    // permuted word e = head*32 + d/2 covers orig cols (2d+head, 2d+2+head), d even
    for (int i = tid; i < 128 * 64; i += 256) {
        int m = i >> 6, e = i & 63;
        int head = e >> 5, d = (e & 31) * 2;
        int c0 = 2 * d + head;
        float v0 = smf[m * 129 + c0];
        float v1 = smf[m * 129 + c0 + 2];
        uint32 hw = pkbf(v0, v1);
        uint32 lw = pkbf(v0 - bflo(hw), v1 - bfhi(hw));
        size_t o = (size_t)(m0 + m) * 384 + (n0 >> 1) + e;
        g_qkvh[o] = hw;
        g_qkvl[o] = lw;
    }
}

// ---------------- 5) Proj GEMM -> channel-major fp32 out + bias ----------------
__global__ void __launch_bounds__(256) gemm_proj_bf(const float* __restrict__ Pb,
                                                    float* __restrict__ out) {
    float acc[4][4][4] = {};
    int m0 = blockIdx.y * 128;
    int n0 = blockIdx.x * 128;
    bf_mainloop(g_xch, g_xcl, g_pwh, g_pwl, m0, n0, acc);
    const float* smf = (const float*)smw;
    int tid = threadIdx.x;
    int b  = m0 >> 14;
    int pp = m0 & (HW - 1);
    int mm = tid & 127;
    int oh = tid >> 7;
    float* Op = out + (size_t)b * C_ * HW + pp + mm;
    #pragma unroll 4
    for (int oo = 0; oo < 64; oo++) {
        int o = n0 + oh * 64 + oo;
        Op[(size_t)o * HW] = smf[mm * 129 + oh * 64 + oo] + Pb[o];
    }
}

// ---------------- 3) LePE (templated branch, reads bf16 planes) ----------------
template<int BR>
__global__ void lepe_t(const float* __restrict__ wt, const float* __restrict__ bs) {
    constexpr int HSP = (BR == 0) ? 128 : 4;
    constexpr int WSP = (BR == 0) ? 4   : 128;
    int cc  = threadIdx.x;
    int s   = blockIdx.x * blockDim.y + threadIdx.y;
    int win = blockIdx.y;
    const float* w = wt + cc * 9;
    float bias = bs[cc];
    int i = s / WSP, j = s % WSP;
    int vcol = 512 + BR * 128 + ((cc & 1) << 6) + (cc >> 1);
    int vw   = vcol >> 1;
    int vh   = vcol & 1;
    float acc = bias;
    #pragma unroll
    for (int ki = 0; ki < 3; ki++) {
        int ii = i + ki - 1;
        if (ii < 0 || ii >= HSP) continue;
        #pragma unroll
        for (int kj = 0; kj < 3; kj++) {
            int jj = j + kj - 1;
            if (jj < 0 || jj >= WSP) continue;
            int tn = win_tok<BR>(win, ii * WSP + jj);
            uint32 wh = g_qkvh[(size_t)tn * 384 + vw];
            uint32 wl = g_qkvl[(size_t)tn * 384 + vw];
            float v = (vh ? bfhi(wh) : bflo(wh)) + (vh ? bfhi(wl) : bflo(wl));
            acc += w[ki * 3 + kj] * v;
        }
    }
    int t = win_tok<BR>(win, s);
    g_xc[(size_t)t * C_ + BR * 128 + cc] = acc;
}

// ---------------- 4) Flash attention, bf16 hi/lo mma ----------------
// block: 128 q rows x (head, win). 256 thr / 8 warps, warp = 16 rows.
// smem words: QH 0 (128*36), QL 4608, KH 9216 (64*36), KL 11520, VH 13824, VL 16128
#define AQH 0
#define AQL 4608
#define AKH 9216
#define AKL 11520
#define AVH 13824
#define AVL 16128
#define SMEM_ATTN_BYTES (18432 * 4)

extern __shared__ uint32 smaw[];
template<int BR>
__global__ void __launch_bounds__(256, 2) attn_flash() {
    int qt   = blockIdx.x;              // 0..3 (128 rows each)
    int head = blockIdx.y;              // 0..1
    int win  = blockIdx.z;              // 0..127
    int tid  = threadIdx.x;
    int wid  = tid >> 5, lane = tid & 31;
    int grp  = lane >> 2, tig = lane & 3;
    int basew = BR * 64 + head * 32;    // word offset of this (br,head) d-block
    uint32 smbase = smem_u32(smaw);

    // ---- Q tile: 128 rows x 32 words, both planes ----
    for (int idx = tid; idx < 4096; idx += 256) {
        int r = idx >> 5, w = idx & 31;
        int t = win_tok<BR>(win, qt * 128 + r);
        size_t g = (size_t)t * 384 + basew + w;
        smaw[AQH + r * 36 + w] = g_qkvh[g];
        smaw[AQL + r * 36 + w] = g_qkvl[g];
    }
    __syncthreads();

    // preload Q fragments (rows wid*16 + grp / +8)
    uint32 qh[4][4], ql[4][4];
    {
        int rb = (wid * 16 + grp) * 36 + tig;
        #pragma unroll
        for (int ks = 0; ks < 4; ks++) {
            int o = rb + ks * 8;
            qh[ks][0] = smaw[AQH + o];       qh[ks][1] = smaw[AQH + o + 288];
            qh[ks][2] = smaw[AQH + o + 4];   qh[ks][3] = smaw[AQH + o + 292];
            ql[ks][0] = smaw[AQL + o];       ql[ks][1] = smaw[AQL + o + 288];
            ql[ks][2] = smaw[AQL + o + 4];   ql[ks][3] = smaw[AQL + o + 292];
        }
    }

    float o_acc[8][4] = {};
    float m0 = -1e30f, m1 = -1e30f, l0 = 0.f, l1 = 0.f;

    for (int ck = 0; ck < 8; ck++) {
        __syncthreads();
        // K and V chunks (64 keys), coalesced [key][d]
        for (int idx = tid; idx < 2048; idx += 256) {
            int r = idx >> 5, w = idx & 31;
            int t = win_tok<BR>(win, ck * 64 + r);
            size_t gk = (size_t)t * 384 + 128 + basew + w;
            size_t gv = (size_t)t * 384 + 256 + basew + w;
            smaw[AKH + r * 36 + w] = g_qkvh[gk];
            smaw[AKL + r * 36 + w] = g_qkvl[gk];
            smaw[AVH + r * 36 + w] = g_qkvh[gv];
            smaw[AVL + r * 36 + w] = g_qkvl[gv];
        }
        __syncthreads();

        // ---- S = Q K^T ----
        float s[8][4];
        #pragma unroll
        for (int j = 0; j < 8; j++) {
            s[j][0] = s[j][1] = s[j][2] = s[j][3] = 0.f;
            #pragma unroll
            for (int ks = 0; ks < 4; ks++) {
                int nb = (j * 8 + grp) * 36 + ks * 8 + tig;
                uint32 bh0 = smaw[AKH + nb], bh1 = smaw[AKH + nb + 4];
                uint32 bl0 = smaw[AKL + nb], bl1 = smaw[AKL + nb + 4];
                mmabf(s[j], qh[ks], bh0, bh1);
                mmabf(s[j], qh[ks], bl0, bl1);
                mmabf(s[j], ql[ks], bh0, bh1);
            }
            s[j][0] *= SCALE; s[j][1] *= SCALE; s[j][2] *= SCALE; s[j][3] *= SCALE;
        }

        // ---- online softmax ----
        float mx0 = s[0][0], mx1 = s[0][2];
        #pragma unroll
        for (int j = 0; j < 8; j++) {
            mx0 = fmaxf(mx0, fmaxf(s[j][0], s[j][1]));
            mx1 = fmaxf(mx1, fmaxf(s[j][2], s[j][3]));
        }
        mx0 = fmaxf(mx0, __shfl_xor_sync(0xffffffffu, mx0, 1));
        mx0 = fmaxf(mx0, __shfl_xor_sync(0xffffffffu, mx0, 2));
        mx1 = fmaxf(mx1, __shfl_xor_sync(0xffffffffu, mx1, 1));
        mx1 = fmaxf(mx1, __shfl_xor_sync(0xffffffffu, mx1, 2));
        float mn0 = fmaxf(m0, mx0), mn1 = fmaxf(m1, mx1);
        float sf0 = __expf(m0 - mn0), sf1 = __expf(m1 - mn1);
        m0 = mn0; m1 = mn1;
        float rs0 = 0.f, rs1 = 0.f;
        #pragma unroll
        for (int j = 0; j < 8; j++) {
            s[j][0] = __expf(s[j][0] - m0); rs0 += s[j][0];
            s[j][1] = __expf(s[j][1] - m0); rs0 += s[j][1];
            s[j][2] = __expf(s[j][2] - m1); rs1 += s[j][2];
            s[j][3] = __expf(s[j][3] - m1); rs1 += s[j][3];
        }
        rs0 += __shfl_xor_sync(0xffffffffu, rs0, 1);
        rs0 += __shfl_xor_sync(0xffffffffu, rs0, 2);
        rs1 += __shfl_xor_sync(0xffffffffu, rs1, 1);
        rs1 += __shfl_xor_sync(0xffffffffu, rs1, 2);
        l0 = l0 * sf0 + rs0;
        l1 = l1 * sf1 + rs1;
        #pragma unroll
        for (int j = 0; j < 8; j++) {
            o_acc[j][0] *= sf0; o_acc[j][1] *= sf0;
            o_acc[j][2] *= sf1; o_acc[j][3] *= sf1;
        }

        // ---- P fragments (bf16 hi/lo) ----
        uint32 ph[4][4], pl[4][4];
        #pragma unroll
        for (int ks = 0; ks < 4; ks++) {
            int j0 = 2 * ks, j1 = 2 * ks + 1;
            ph[ks][0] = pkbf(s[j0][0], s[j0][1]);
            ph[ks][1] = pkbf(s[j0][2], s[j0][3]);
            ph[ks][2] = pkbf(s[j1][0], s[j1][1]);
            ph[ks][3] = pkbf(s[j1][2], s[j1][3]);
            pl[ks][0] = pkbf(s[j0][0] - bflo(ph[ks][0]), s[j0][1] - bfhi(ph[ks][0]));
            pl[ks][1] = pkbf(s[j0][2] - bflo(ph[ks][1]), s[j0][3] - bfhi(ph[ks][1]));
            pl[ks][2] = pkbf(s[j1][0] - bflo(ph[ks][2]), s[j1][1] - bfhi(ph[ks][2]));
            pl[ks][3] = pkbf(s[j1][2] - bflo(ph[ks][3]), s[j1][3] - bfhi(ph[ks][3]));
        }

        // ---- O += P V  (V via ldmatrix.trans) ----
        int p2 = lane >> 3, rr = lane & 7;
        #pragma unroll
        for (int jp = 0; jp < 4; jp++) {
            #pragma unroll
            for (int ks = 0; ks < 4; ks++) {
                int key = 16 * ks + ((p2 & 1) << 3) + rr;
                int dw  = (16 * jp + ((p2 >> 1) << 3)) >> 1;
                uint32 aH = smbase + (AVH + key * 36 + dw) * 4;
                uint32 aL = smbase + (AVL + key * 36 + dw) * 4;
                uint32 vh0, vh1, vh2, vh3, vl0, vl1, vl2, vl3;
                ldmT(vh0, vh1, vh2, vh3, aH);
                ldmT(vl0, vl1, vl2, vl3, aL);
                mmabf(o_acc[2 * jp],     ph[ks], vh0, vh1);
                mmabf(o_acc[2 * jp],     ph[ks], vl0, vl1);
                mmabf(o_acc[2 * jp],     pl[ks], vh0, vh1);
                mmabf(o_acc[2 * jp + 1], ph[ks], vh2, vh3);
                mmabf(o_acc[2 * jp + 1], ph[ks], vl2, vl3);
                mmabf(o_acc[2 * jp + 1], pl[ks], vh2, vh3);
            }
        }
    }

    // ---- epilogue: normalize, accumulate onto LePE ----
    float i0 = 1.0f / l0, i1 = 1.0f / l1;
    int r0 = qt * 128 + wid * 16 + grp;
    int t0 = win_tok<BR>(win, r0);
    int t1 = win_tok<BR>(win, r0 + 8);
    size_t g0 = (size_t)t0 * C_ + BR * 128 + head;
    size_t g1 = (size_t)t1 * C_ + BR * 128 + head;
    #pragma unroll
    for (int j = 0; j < 8; j++) {
        int d = j * 8 + 2 * tig;
        g_xc[g0 + 2 * d]       += o_acc[j][0] * i0;
        g_xc[g0 + 2 * (d + 1)] += o_acc[j][1] * i0;
        g_xc[g1 + 2 * d]       += o_acc[j][2] * i1;
        g_xc[g1 + 2 * (d + 1)] += o_acc[j][3] * i1;
    }
}

// ---------------- launch ----------------
extern "C" void kernel_launch(void* const* d_in, const int* in_sizes, int n_in,
                              void* d_out, int out_size) {
    const float* x       = (const float*)d_in[0];
    const float* ln_g    = (const float*)d_in[1];
    const float* ln_b    = (const float*)d_in[2];
    const float* w_qkv   = (const float*)d_in[3];
    const float* lepe_w1 = (const float*)d_in[4];
    const float* lepe_b1 = (const float*)d_in[5];
    const float* lepe_w2 = (const float*)d_in[6];
    const float* lepe_b2 = (const float*)d_in[7];
    const float* proj_w  = (const float*)d_in[8];
    const float* proj_b  = (const float*)d_in[9];
    float* out = (float*)d_out;

    cudaFuncSetAttribute(gemm_qkv_bf,  cudaFuncAttributeMaxDynamicSharedMemorySize, SMEM_GEMM_BYTES);
    cudaFuncSetAttribute(gemm_proj_bf, cudaFuncAttributeMaxDynamicSharedMemorySize, SMEM_GEMM_BYTES);
    cudaFuncSetAttribute(attn_flash<0>, cudaFuncAttributeMaxDynamicSharedMemorySize, SMEM_ATTN_BYTES);
    cudaFuncSetAttribute(attn_flash<1>, cudaFuncAttributeMaxDynamicSharedMemorySize, SMEM_ATTN_BYTES);

    ln_kernel   <<< NTOK / 32, 256 >>>(x, ln_g, ln_b);
    w_split     <<< 384, 256 >>>(w_qkv, proj_w);
    gemm_qkv_bf <<< dim3(6, 512), 256, SMEM_GEMM_BYTES >>>();
    lepe_t<0>   <<< dim3(128, 128), dim3(128, 4) >>>(lepe_w1, lepe_b1);
    lepe_t<1>   <<< dim3(128, 128), dim3(128, 4) >>>(lepe_w2, lepe_b2);
    attn_flash<0> <<< dim3(4, 2, 128), 256, SMEM_ATTN_BYTES >>>();
    attn_flash<1> <<< dim3(4, 2, 128), 256, SMEM_ATTN_BYTES >>>();
    xc_split    <<< (NTOK * 128) / 256, 256 >>>();
    gemm_proj_bf <<< dim3(2, 512), 256, SMEM_GEMM_BYTES >>>(proj_b, out);
}

// round 9
// speedup vs baseline: 2.9605x; 1.1084x over previous
#include <cuda_runtime.h>
#include <math.h>

#define B_    4
#define C_    256
#define H_    128
#define W_    128
#define HW    (H_*W_)          // 16384
#define NTOK  (B_*HW)          // 65536
#define SCALE 0.08838834764831845f
#define EPS   1e-4f

typedef unsigned long long ull;
typedef unsigned int uint32;

// ---------------- bf16 helpers ----------------
__device__ __forceinline__ uint32 pkbf(float lo, float hi) {
    uint32 d; asm("cvt.rn.bf16x2.f32 %0, %1, %2;" : "=r"(d) : "f"(hi), "f"(lo)); return d;
}
__device__ __forceinline__ float bflo(uint32 w){ return __uint_as_float(w << 16); }
__device__ __forceinline__ float bfhi(uint32 w){ return __uint_as_float(w & 0xffff0000u); }

__device__ __forceinline__ void mmabf(float* d, const uint32* a, uint32 b0, uint32 b1) {
    asm volatile("mma.sync.aligned.m16n8k16.row.col.f32.bf16.bf16.f32 "
        "{%0,%1,%2,%3}, {%4,%5,%6,%7}, {%8,%9}, {%0,%1,%2,%3};"
        : "+f"(d[0]), "+f"(d[1]), "+f"(d[2]), "+f"(d[3])
        : "r"(a[0]), "r"(a[1]), "r"(a[2]), "r"(a[3]), "r"(b0), "r"(b1));
}
__device__ __forceinline__ void ldmT(uint32& r0, uint32& r1, uint32& r2, uint32& r3, uint32 addr) {
    asm volatile("ldmatrix.sync.aligned.m8n8.x4.trans.shared.b16 {%0,%1,%2,%3}, [%4];"
        : "=r"(r0), "=r"(r1), "=r"(r2), "=r"(r3) : "r"(addr));
}
__device__ __forceinline__ uint32 smem_u32(const void* p) {
    uint32 a;
    asm("{ .reg .u64 t; cvta.to.shared.u64 t, %1; cvt.u32.u64 %0, t; }" : "=r"(a) : "l"(p));
    return a;
}

// ---------------- scratch (bf16 planes as packed uint32 words) ----------------
__device__ uint32 g_xnh[(size_t)NTOK * 128];
__device__ uint32 g_xnl[(size_t)NTOK * 128];
__device__ uint32 g_qkvh[(size_t)NTOK * 384];   // [t][384w], head-deinterleaved
__device__ uint32 g_qkvl[(size_t)NTOK * 384];
__device__ float  g_xc [(size_t)NTOK * C_];     // lepe (fp32), PERMUTED channels [br][head][d]
__device__ uint32 g_xch[(size_t)NTOK * 128];    // attn+lepe hi (permuted)
__device__ uint32 g_xcl[(size_t)NTOK * 128];
__device__ uint32 g_wqh[768 * 128];
__device__ uint32 g_wql[768 * 128];
__device__ uint32 g_pwh[256 * 128];             // proj W, columns permuted to match xc
__device__ uint32 g_pwl[256 * 128];

template<int BR>
__device__ __forceinline__ int win_tok(int win, int s) {
    int b  = win >> 5;
    int wi = win & 31;
    int y, x;
    if (BR == 0) { y = s >> 2;               x = (wi << 2) + (s & 3); }
    else         { y = (wi << 2) + (s >> 7); x = s & 127; }
    return b * HW + y * W_ + x;
}

// ---------------- 1) LayerNorm -> bf16 hi/lo planes ----------------
__global__ void __launch_bounds__(256) ln_kernel(const float* __restrict__ x,
                                                 const float* __restrict__ gam,
                                                 const float* __restrict__ bet) {
    __shared__ float xs[C_][33];
    __shared__ float mu_s[32], rs_s[32];
    int tid = threadIdx.x;
    int tx = tid & 31, ty = tid >> 5;
    int t0 = blockIdx.x * 32;
    int b  = t0 / HW;
    int pp = t0 - b * HW;
    const float* xb = x + (size_t)b * C_ * HW + pp + tx;
    #pragma unroll
    for (int c = ty; c < C_; c += 8)
        xs[c][tx] = xb[(size_t)c * HW];
    __syncthreads();
    if (tid < 32) {
        float s = 0.f, s2 = 0.f;
        #pragma unroll 8
        for (int c = 0; c < C_; c++) { float v = xs[c][tid]; s += v; s2 += v * v; }
        float mu  = s * (1.0f / C_);
        float var = s2 * (1.0f / C_) - mu * mu;
        mu_s[tid] = mu;
        rs_s[tid] = rsqrtf(var + EPS);
    }
    __syncthreads();
    for (int idx = tid; idx < 32 * 128; idx += 256) {
        int c2 = idx & 127, tk = idx >> 7;
        int c = c2 * 2;
        float v0 = (xs[c][tk]     - mu_s[tk]) * rs_s[tk] * gam[c]     + bet[c];
        float v1 = (xs[c + 1][tk] - mu_s[tk]) * rs_s[tk] * gam[c + 1] + bet[c + 1];
        uint32 hw = pkbf(v0, v1);
        uint32 lw = pkbf(v0 - bflo(hw), v1 - bfhi(hw));
        size_t o = (size_t)(t0 + tk) * 128 + c2;
        g_xnh[o] = hw;
        g_xnl[o] = lw;
    }
}

// ---------------- 1b) weight splits (proj columns permuted) ----------------
__global__ void __launch_bounds__(256) w_split(const float* __restrict__ wqkv,
                                               const float* __restrict__ projw) {
    int idx = blockIdx.x * 256 + threadIdx.x;
    if (idx < 768 * 128) {
        int n = idx >> 7, kw = idx & 127;
        float v0 = wqkv[(size_t)(2 * kw) * 768 + n];
        float v1 = wqkv[(size_t)(2 * kw + 1) * 768 + n];
        uint32 hw = pkbf(v0, v1);
        g_wqh[idx] = hw;
        g_wql[idx] = pkbf(v0 - bflo(hw), v1 - bfhi(hw));
    }
    if (idx < 256 * 128) {
        int o = idx >> 7, kw = idx & 127;
        int pc = 2 * kw;                      // permuted channel
        int br = pc >> 7, rm = pc & 127;
        int head = rm >> 6, d = rm & 63;
        int c0 = br * 128 + 2 * d + head;     // original channel
        float v0 = projw[(size_t)o * 256 + c0];
        float v1 = projw[(size_t)o * 256 + c0 + 2];
        uint32 hw = pkbf(v0, v1);
        g_pwh[idx] = hw;
        g_pwl[idx] = pkbf(v0 - bflo(hw), v1 - bfhi(hw));
    }
}

// ---------------- bf16 3-product GEMM core ----------------
#define GAH 0
#define GAL 2560
#define GBH 5120
#define GBL 7680
#define SMEM_GEMM_BYTES (16512 * 4)

extern __shared__ uint32 smw[];

__device__ __forceinline__ void bf_mainloop(
        const uint32* __restrict__ Ah, const uint32* __restrict__ Al,
        const uint32* __restrict__ Bh, const uint32* __restrict__ Bl,
        int m0, int n0, float acc[4][4][4]) {
    int tid  = threadIdx.x;
    int wid  = tid >> 5, lane = tid & 31;
    int wm   = (wid & 1) * 64;
    int wn   = (wid >> 1) * 32;
    int grp  = lane >> 2, tig = lane & 3;

    for (int ck = 0; ck < 8; ck++) {
        int k0w = ck * 16;
        __syncthreads();
        #pragma unroll
        for (int idx = tid; idx < 2048; idx += 256) {
            int r = idx >> 4, w = idx & 15;
            int so = r * 20 + w;
            size_t ga = (size_t)(m0 + r) * 128 + k0w + w;
            size_t gb = (size_t)(n0 + r) * 128 + k0w + w;
            smw[GAH + so] = Ah[ga];
            smw[GAL + so] = Al[ga];
            smw[GBH + so] = Bh[gb];
            smw[GBL + so] = Bl[gb];
        }
        __syncthreads();
        #pragma unroll
        for (int ks = 0; ks < 2; ks++) {
            uint32 bh[4][2], bl[4][2];
            #pragma unroll
            for (int j = 0; j < 4; j++) {
                int nb = (wn + j * 8 + grp) * 20 + ks * 8 + tig;
                bh[j][0] = smw[GBH + nb]; bh[j][1] = smw[GBH + nb + 4];
                bl[j][0] = smw[GBL + nb]; bl[j][1] = smw[GBL + nb + 4];
            }
            #pragma unroll
            for (int i = 0; i < 4; i++) {
                int mb = (wm + i * 16 + grp) * 20 + ks * 8 + tig;
                uint32 ah[4], al[4];
                ah[0] = smw[GAH + mb];        ah[1] = smw[GAH + mb + 160];
                ah[2] = smw[GAH + mb + 4];    ah[3] = smw[GAH + mb + 164];
                al[0] = smw[GAL + mb];        al[1] = smw[GAL + mb + 160];
                al[2] = smw[GAL + mb + 4];    al[3] = smw[GAL + mb + 164];
                #pragma unroll
                for (int j = 0; j < 4; j++) {
                    mmabf(acc[i][j], ah, bh[j][0], bh[j][1]);
                    mmabf(acc[i][j], ah, bl[j][0], bl[j][1]);
                    mmabf(acc[i][j], al, bh[j][0], bh[j][1]);
                }
            }
        }
    }
    __syncthreads();
    float* smf = (float*)smw;
    #pragma unroll
    for (int i = 0; i < 4; i++)
        #pragma unroll
        for (int j = 0; j < 4; j++) {
            int m = wm + i * 16 + grp;
            int n = wn + j * 8 + tig * 2;
            smf[m * 129 + n]           = acc[i][j][0];
            smf[m * 129 + n + 1]       = acc[i][j][1];
            smf[(m + 8) * 129 + n]     = acc[i][j][2];
            smf[(m + 8) * 129 + n + 1] = acc[i][j][3];
        }
    __syncthreads();
}

// ---------------- 2) QKV GEMM -> permuted bf16 planes (q pre-scaled) ----------------
__global__ void __launch_bounds__(256) gemm_qkv_bf() {
    float acc[4][4][4] = {};
    int m0 = blockIdx.y * 128;
    int n0 = blockIdx.x * 128;
    bf_mainloop(g_xnh, g_xnl, g_wqh, g_wql, m0, n0, acc);
    const float* smf = (const float*)smw;
    int tid = threadIdx.x;
    float sc = (n0 < 256) ? SCALE : 1.0f;    // fold attention scale into Q
    for (int i = tid; i < 128 * 64; i += 256) {
        int m = i >> 6, e = i & 63;
        int head = e >> 5, d = (e & 31) * 2;
        int c0 = 2 * d + head;
        float v0 = smf[m * 129 + c0] * sc;
        float v1 = smf[m * 129 + c0 + 2] * sc;
        uint32 hw = pkbf(v0, v1);
        uint32 lw = pkbf(v0 - bflo(hw), v1 - bfhi(hw));
        size_t o = (size_t)(m0 + m) * 384 + (n0 >> 1) + e;
        g_qkvh[o] = hw;
        g_qkvl[o] = lw;
    }
}

// ---------------- 5) Proj GEMM -> channel-major fp32 out + bias ----------------
__global__ void __launch_bounds__(256) gemm_proj_bf(const float* __restrict__ Pb,
                                                    float* __restrict__ out) {
    float acc[4][4][4] = {};
    int m0 = blockIdx.y * 128;
    int n0 = blockIdx.x * 128;
    bf_mainloop(g_xch, g_xcl, g_pwh, g_pwl, m0, n0, acc);
    const float* smf = (const float*)smw;
    int tid = threadIdx.x;
    int b  = m0 >> 14;
    int pp = m0 & (HW - 1);
    int mm = tid & 127;
    int oh = tid >> 7;
    float* Op = out + (size_t)b * C_ * HW + pp + mm;
    #pragma unroll 4
    for (int oo = 0; oo < 64; oo++) {
        int o = n0 + oh * 64 + oo;
        Op[(size_t)o * HW] = smf[mm * 129 + oh * 64 + oo] + Pb[o];
    }
}

// ---------------- 3) LePE — image-neighbor form, 2 channels/thread ----------------
// thread: token t, word ew (0..63). v word = 256 + BR*64 + ew.
// permuted out channels pc = (2ew, 2ew+1); conv channels cc0 = 4*(ew&31)+(ew>>5), cc0+2.
template<int BR>
__global__ void __launch_bounds__(256) lepe_t(const float* __restrict__ wt,
                                              const float* __restrict__ bs) {
    __shared__ float ws[128 * 9];
    __shared__ float bss[128];
    int tid = threadIdx.x;
    for (int i = tid; i < 128 * 9; i += 256) ws[i] = wt[i];
    if (tid < 128) bss[tid] = bs[tid];
    __syncthreads();
    int ew = tid & 63;
    int t  = blockIdx.x * 4 + (tid >> 6);
    int y  = (t >> 7) & 127, x = t & 127;
    int vw = 256 + BR * 64 + ew;
    int cc0 = 4 * (ew & 31) + (ew >> 5);
    int cc1 = cc0 + 2;
    float a0 = bss[cc0], a1 = bss[cc1];
    bool um, dm, lm, rm;
    if (BR == 0) { um = y > 0;       dm = y < 127;      lm = (x & 3) > 0; rm = (x & 3) < 3; }
    else         { um = (y & 3) > 0; dm = (y & 3) < 3;  lm = x > 0;       rm = x < 127; }
    #pragma unroll
    for (int ki = 0; ki < 3; ki++) {
        if (ki == 0 && !um) continue;
        if (ki == 2 && !dm) continue;
        int tb = t + (ki - 1) * W_;
        #pragma unroll
        for (int kj = 0; kj < 3; kj++) {
            if (kj == 0 && !lm) continue;
            if (kj == 2 && !rm) continue;
            size_t g = (size_t)(tb + kj - 1) * 384 + vw;
            uint32 hw = g_qkvh[g], lw = g_qkvl[g];
            float w0 = ws[cc0 * 9 + ki * 3 + kj];
            float w1 = ws[cc1 * 9 + ki * 3 + kj];
            a0 += w0 * (bflo(hw) + bflo(lw));
            a1 += w1 * (bfhi(hw) + bfhi(lw));
        }
    }
    *(float2*)&g_xc[(size_t)t * 256 + BR * 128 + 2 * ew] = make_float2(a0, a1);
}

// ---------------- 4) Flash attention, bf16 hi/lo mma ----------------
#define AQH 0
#define AQL 4608
#define AKH 9216
#define AKL 11520
#define AVH 13824
#define AVL 16128
#define SMEM_ATTN_BYTES (18432 * 4)

extern __shared__ uint32 smaw[];
template<int BR>
__global__ void __launch_bounds__(256, 2) attn_flash() {
    int qt   = blockIdx.x;
    int head = blockIdx.y;
    int win  = blockIdx.z;
    int tid  = threadIdx.x;
    int wid  = tid >> 5, lane = tid & 31;
    int grp  = lane >> 2, tig = lane & 3;
    int basew = BR * 64 + head * 32;
    uint32 smbase = smem_u32(smaw);

    for (int idx = tid; idx < 4096; idx += 256) {
        int r = idx >> 5, w = idx & 31;
        int t = win_tok<BR>(win, qt * 128 + r);
        size_t g = (size_t)t * 384 + basew + w;
        smaw[AQH + r * 36 + w] = g_qkvh[g];
        smaw[AQL + r * 36 + w] = g_qkvl[g];
    }
    __syncthreads();

    uint32 qh[4][4], ql[4][4];
    {
        int rb = (wid * 16 + grp) * 36 + tig;
        #pragma unroll
        for (int ks = 0; ks < 4; ks++) {
            int o = rb + ks * 8;
            qh[ks][0] = smaw[AQH + o];       qh[ks][1] = smaw[AQH + o + 288];
            qh[ks][2] = smaw[AQH + o + 4];   qh[ks][3] = smaw[AQH + o + 292];
            ql[ks][0] = smaw[AQL + o];       ql[ks][1] = smaw[AQL + o + 288];
            ql[ks][2] = smaw[AQL + o + 4];   ql[ks][3] = smaw[AQL + o + 292];
        }
    }

    float o_acc[8][4] = {};
    float m0 = -1e30f, m1 = -1e30f, l0 = 0.f, l1 = 0.f;

    for (int ck = 0; ck < 8; ck++) {
        __syncthreads();
        for (int idx = tid; idx < 2048; idx += 256) {
            int r = idx >> 5, w = idx & 31;
            int t = win_tok<BR>(win, ck * 64 + r);
            size_t gk = (size_t)t * 384 + 128 + basew + w;
            size_t gv = (size_t)t * 384 + 256 + basew + w;
            smaw[AKH + r * 36 + w] = g_qkvh[gk];
            smaw[AKL + r * 36 + w] = g_qkvl[gk];
            smaw[AVH + r * 36 + w] = g_qkvh[gv];
            smaw[AVL + r * 36 + w] = g_qkvl[gv];
        }
        __syncthreads();

        float s[8][4];
        #pragma unroll
        for (int j = 0; j < 8; j++) {
            s[j][0] = s[j][1] = s[j][2] = s[j][3] = 0.f;
            #pragma unroll
            for (int ks = 0; ks < 4; ks++) {
                int nb = (j * 8 + grp) * 36 + ks * 8 + tig;
                uint32 bh0 = smaw[AKH + nb], bh1 = smaw[AKH + nb + 4];
                uint32 bl0 = smaw[AKL + nb], bl1 = smaw[AKL + nb + 4];
                mmabf(s[j], qh[ks], bh0, bh1);
                mmabf(s[j], qh[ks], bl0, bl1);
                mmabf(s[j], ql[ks], bh0, bh1);
            }
        }

        float mx0 = s[0][0], mx1 = s[0][2];
        #pragma unroll
        for (int j = 0; j < 8; j++) {
            mx0 = fmaxf(mx0, fmaxf(s[j][0], s[j][1]));
            mx1 = fmaxf(mx1, fmaxf(s[j][2], s[j][3]));
        }
        mx0 = fmaxf(mx0, __shfl_xor_sync(0xffffffffu, mx0, 1));
        mx0 = fmaxf(mx0, __shfl_xor_sync(0xffffffffu, mx0, 2));
        mx1 = fmaxf(mx1, __shfl_xor_sync(0xffffffffu, mx1, 1));
        mx1 = fmaxf(mx1, __shfl_xor_sync(0xffffffffu, mx1, 2));
        float mn0 = fmaxf(m0, mx0), mn1 = fmaxf(m1, mx1);
        float sf0 = __expf(m0 - mn0), sf1 = __expf(m1 - mn1);
        m0 = mn0; m1 = mn1;
        float rs0 = 0.f, rs1 = 0.f;
        #pragma unroll
        for (int j = 0; j < 8; j++) {
            s[j][0] = __expf(s[j][0] - m0); rs0 += s[j][0];
            s[j][1] = __expf(s[j][1] - m0); rs0 += s[j][1];
            s[j][2] = __expf(s[j][2] - m1); rs1 += s[j][2];
            s[j][3] = __expf(s[j][3] - m1); rs1 += s[j][3];
        }
        rs0 += __shfl_xor_sync(0xffffffffu, rs0, 1);
        rs0 += __shfl_xor_sync(0xffffffffu, rs0, 2);
        rs1 += __shfl_xor_sync(0xffffffffu, rs1, 1);
        rs1 += __shfl_xor_sync(0xffffffffu, rs1, 2);
        l0 = l0 * sf0 + rs0;
        l1 = l1 * sf1 + rs1;
        #pragma unroll
        for (int j = 0; j < 8; j++) {
            o_acc[j][0] *= sf0; o_acc[j][1] *= sf0;
            o_acc[j][2] *= sf1; o_acc[j][3] *= sf1;
        }

        uint32 ph[4][4], pl[4][4];
        #pragma unroll
        for (int ks = 0; ks < 4; ks++) {
            int j0 = 2 * ks, j1 = 2 * ks + 1;
            ph[ks][0] = pkbf(s[j0][0], s[j0][1]);
            ph[ks][1] = pkbf(s[j0][2], s[j0][3]);
            ph[ks][2] = pkbf(s[j1][0], s[j1][1]);
            ph[ks][3] = pkbf(s[j1][2], s[j1][3]);
            pl[ks][0] = pkbf(s[j0][0] - bflo(ph[ks][0]), s[j0][1] - bfhi(ph[ks][0]));
            pl[ks][1] = pkbf(s[j0][2] - bflo(ph[ks][1]), s[j0][3] - bfhi(ph[ks][1]));
            pl[ks][2] = pkbf(s[j1][0] - bflo(ph[ks][2]), s[j1][1] - bfhi(ph[ks][2]));
            pl[ks][3] = pkbf(s[j1][2] - bflo(ph[ks][3]), s[j1][3] - bfhi(ph[ks][3]));
        }

        int p2 = lane >> 3, rr = lane & 7;
        #pragma unroll
        for (int jp = 0; jp < 4; jp++) {
            #pragma unroll
            for (int ks = 0; ks < 4; ks++) {
                int key = 16 * ks + ((p2 & 1) << 3) + rr;
                int dw  = (16 * jp + ((p2 >> 1) << 3)) >> 1;
                uint32 aH = smbase + (AVH + key * 36 + dw) * 4;
                uint32 aL = smbase + (AVL + key * 36 + dw) * 4;
                uint32 vh0, vh1, vh2, vh3, vl0, vl1, vl2, vl3;
                ldmT(vh0, vh1, vh2, vh3, aH);
                ldmT(vl0, vl1, vl2, vl3, aL);
                mmabf(o_acc[2 * jp],     ph[ks], vh0, vh1);
                mmabf(o_acc[2 * jp],     ph[ks], vl0, vl1);
                mmabf(o_acc[2 * jp],     pl[ks], vh0, vh1);
                mmabf(o_acc[2 * jp + 1], ph[ks], vh2, vh3);
                mmabf(o_acc[2 * jp + 1], ph[ks], vl2, vl3);
                mmabf(o_acc[2 * jp + 1], pl[ks], vh2, vh3);
            }
        }
    }

    // ---- epilogue: + LePE, produce bf16 hi/lo planes directly (permuted layout) ----
    float i0 = 1.0f / l0, i1 = 1.0f / l1;
    int r0 = qt * 128 + wid * 16 + grp;
    int t0 = win_tok<BR>(win, r0);
    int t1 = win_tok<BR>(win, r0 + 8);
    int cb  = BR * 128 + head * 64;
    int wb0 = BR * 64 + head * 32;
    #pragma unroll
    for (int j = 0; j < 8; j++) {
        int d = j * 8 + 2 * tig;
        float2 le0 = *(const float2*)&g_xc[(size_t)t0 * 256 + cb + d];
        float2 le1 = *(const float2*)&g_xc[(size_t)t1 * 256 + cb + d];
        float a0 = le0.x + o_acc[j][0] * i0;
        float a1 = le0.y + o_acc[j][1] * i0;
        float b0 = le1.x + o_acc[j][2] * i1;
        float b1 = le1.y + o_acc[j][3] * i1;
        int wx = wb0 + j * 4 + tig;
        uint32 h0 = pkbf(a0, a1);
        g_xch[(size_t)t0 * 128 + wx] = h0;
        g_xcl[(size_t)t0 * 128 + wx] = pkbf(a0 - bflo(h0), a1 - bfhi(h0));
        uint32 h1 = pkbf(b0, b1);
        g_xch[(size_t)t1 * 128 + wx] = h1;
        g_xcl[(size_t)t1 * 128 + wx] = pkbf(b0 - bflo(h1), b1 - bfhi(h1));
    }
}

// ---------------- launch ----------------
extern "C" void kernel_launch(void* const* d_in, const int* in_sizes, int n_in,
                              void* d_out, int out_size) {
    const float* x       = (const float*)d_in[0];
    const float* ln_g    = (const float*)d_in[1];
    const float* ln_b    = (const float*)d_in[2];
    const float* w_qkv   = (const float*)d_in[3];
    const float* lepe_w1 = (const float*)d_in[4];
    const float* lepe_b1 = (const float*)d_in[5];
    const float* lepe_w2 = (const float*)d_in[6];
    const float* lepe_b2 = (const float*)d_in[7];
    const float* proj_w  = (const float*)d_in[8];
    const float* proj_b  = (const float*)d_in[9];
    float* out = (float*)d_out;

    cudaFuncSetAttribute(gemm_qkv_bf,  cudaFuncAttributeMaxDynamicSharedMemorySize, SMEM_GEMM_BYTES);
    cudaFuncSetAttribute(gemm_proj_bf, cudaFuncAttributeMaxDynamicSharedMemorySize, SMEM_GEMM_BYTES);
    cudaFuncSetAttribute(attn_flash<0>, cudaFuncAttributeMaxDynamicSharedMemorySize, SMEM_ATTN_BYTES);
    cudaFuncSetAttribute(attn_flash<1>, cudaFuncAttributeMaxDynamicSharedMemorySize, SMEM_ATTN_BYTES);

    ln_kernel   <<< NTOK / 32, 256 >>>(x, ln_g, ln_b);
    w_split     <<< 384, 256 >>>(w_qkv, proj_w);
    gemm_qkv_bf <<< dim3(6, 512), 256, SMEM_GEMM_BYTES >>>();
    lepe_t<0>   <<< NTOK / 4, 256 >>>(lepe_w1, lepe_b1);
    lepe_t<1>   <<< NTOK / 4, 256 >>>(lepe_w2, lepe_b2);
    attn_flash<0> <<< dim3(4, 2, 128), 256, SMEM_ATTN_BYTES >>>();
    attn_flash<1> <<< dim3(4, 2, 128), 256, SMEM_ATTN_BYTES >>>();
    gemm_proj_bf <<< dim3(2, 512), 256, SMEM_GEMM_BYTES >>>(proj_b, out);
}